// round 12
// baseline (speedup 1.0000x reference)
#include <cuda_runtime.h>

// Problem constants (fixed: B=16, N=8192, C=256, num_points=2048)
#define BB   16
#define NN   8192
#define CC   256
#define MM   2048
#define TT   512           // threads per FPS block (reg cap 128 -> headroom)
#define NW   (TT / 32)     // 16 warps
#define PPT  (NN / TT)     // points per thread = 16
#define NG   4             // groups per warp (128 sorted-contiguous points)

// Scratch: selected indices, written by FPS kernel, read by gather kernel.
__device__ int g_idx[BB * MM];

// Dynamic smem: sq4[NN] float4 (orig-indexed, then rank-indexed after permute)
// | pvi[2*NW] uint2 | initv[NW] | initi[NW] | cent[3*NW] | wext[NW*NG] float2
// | skx[NN] float | ski[NN] int
#define SMEM_BYTES (NN * 16 + 2 * NW * 8 + NW * 4 + NW * 4 + 3 * NW * 4 \
                    + NW * NG * 8 + NN * 4 + NN * 4)

__device__ __forceinline__ float warp_sum(float x) {
    #pragma unroll
    for (int o = 16; o > 0; o >>= 1)
        x += __shfl_xor_sync(0xFFFFFFFFu, x, o);
    return x;
}
__device__ __forceinline__ float warp_min(float x) {
    #pragma unroll
    for (int o = 16; o > 0; o >>= 1)
        x = fminf(x, __shfl_xor_sync(0xFFFFFFFFu, x, o));
    return x;
}
__device__ __forceinline__ float warp_max(float x) {
    #pragma unroll
    for (int o = 16; o > 0; o >>= 1)
        x = fmaxf(x, __shfl_xor_sync(0xFFFFFFFFu, x, o));
    return x;
}

extern "C" __global__ void __launch_bounds__(TT, 1)
fps_kernel(const float* __restrict__ pts,   // [B, 3, N]
           float* __restrict__ out_pts)     // [B, M, 3]
{
    extern __shared__ unsigned char smraw[];
    float4*   sq4   = (float4*)smraw;                  // [NN]
    uint2*    pvi   = (uint2*)(smraw + NN * 16);       // [2*NW] (val,cand) bufs
    unsigned* initv = (unsigned*)(pvi + 2 * NW);       // [NW]
    unsigned* initi = initv + NW;                      // [NW]
    float*    cent  = (float*)(initi + NW);            // [3*NW]
    float2*   wext  = (float2*)(cent + 3 * NW);        // [NW*NG] (xmn, xmx)
    float*    skx   = (float*)(wext + NW * NG);        // [NN] sort keys (x)
    int*      ski   = (int*)(skx + NN);                // [NN] orig indices

    const int b    = blockIdx.x;
    const int tid  = threadIdx.x;
    const int lane = tid & 31;
    const int warp = tid >> 5;

    const float* px = pts + (size_t)b * 3 * NN;
    const float* py = px + NN;
    const float* pz = px + 2 * NN;

    // ---- load (orig layout), centroid sums, sort-key init ----
    float s1 = 0.f, s2 = 0.f, s3 = 0.f;
    #pragma unroll
    for (int k = 0; k < PPT; k++) {
        int n = tid + k * TT;               // coalesced
        float x = px[n], y = py[n], z = pz[n];
        sq4[n] = make_float4(x, y, z, 0.f);
        skx[n] = x; ski[n] = n;
        s1 += x; s2 += y; s3 += z;
    }
    s1 = warp_sum(s1); s2 = warp_sum(s2); s3 = warp_sum(s3);
    if (lane == 0) { cent[warp] = s1; cent[NW + warp] = s2; cent[2 * NW + warp] = s3; }

    // ---- bitonic sort by x (permutation-preserving; sort quality only
    //      affects pruning, never correctness) ----
    for (int k = 2; k <= NN; k <<= 1) {
        for (int j = k >> 1; j > 0; j >>= 1) {
            __syncthreads();
            #pragma unroll 4
            for (int t = tid; t < NN / 2; t += TT) {
                int i = 2 * t - (t & (j - 1));
                int l = i + j;
                bool up = ((i & k) == 0);
                float a = skx[i], c = skx[l];
                bool sw = up ? (a > c) : (a < c);
                if (sw) {
                    skx[i] = c; skx[l] = a;
                    int ta = ski[i]; ski[i] = ski[l]; ski[l] = ta;
                }
            }
        }
    }
    __syncthreads();

    // ---- in-place permute sq4 into RANK order, orig idx bit-stashed in .w.
    //      All reads -> barrier -> all writes (register staging). ----
    float4 stg[PPT];
    {
        const int base = warp * (32 * PPT) + lane;
        #pragma unroll
        for (int k = 0; k < PPT; k++) {
            int r = base + 32 * k;
            int idx = ski[r];
            float4 p = sq4[idx];
            p.w = __uint_as_float((unsigned)idx);
            stg[k] = p;
        }
        __syncthreads();                      // all reads done
        #pragma unroll
        for (int k = 0; k < PPT; k++)
            sq4[base + 32 * k] = stg[k];      // sq4 is now rank-indexed
    }

    // Per-group x-extents (from points actually held) -> smem (rare reads).
    #pragma unroll
    for (int g = 0; g < NG; g++) {
        float mn = fminf(fminf(stg[4 * g].x, stg[4 * g + 1].x),
                         fminf(stg[4 * g + 2].x, stg[4 * g + 3].x));
        float mx = fmaxf(fmaxf(stg[4 * g].x, stg[4 * g + 1].x),
                         fmaxf(stg[4 * g + 2].x, stg[4 * g + 3].x));
        mn = warp_min(mn); mx = warp_max(mx);
        if (lane == 0) wext[warp * NG + g] = make_float2(mn, mx);
    }

    // Centroid finalize (NW=16 valid partials).
    float cx = warp_sum(lane < NW ? cent[lane] : 0.f)          * (1.0f / NN);
    float cy = warp_sum(lane < NW ? cent[NW + lane] : 0.f)     * (1.0f / NN);
    float cz = warp_sum(lane < NW ? cent[2 * NW + lane] : 0.f) * (1.0f / NN);

    // d0 = ||p - centroid||^2, initial farthest (exact plain form).
    // Candidates are composites (origidx << 13) | rank: origidx unique, so
    // min composite == min original index (exact jnp.argmax tie-break), and
    // the rank rides along for the q lookup.
    float dr[PPT];
    float best = -1.0f; unsigned bi = 0xFFFFFFFFu;
    {
        const int base = warp * (32 * PPT) + lane;
        #pragma unroll
        for (int k = 0; k < PPT; k++) {
            float dx = stg[k].x - cx, dy = stg[k].y - cy, dz = stg[k].z - cz;
            float d = __fadd_rn(__fadd_rn(__fmul_rn(dx, dx), __fmul_rn(dy, dy)),
                                __fmul_rn(dz, dz));
            unsigned comp = (__float_as_uint(stg[k].w) << 13)
                          | (unsigned)(base + 32 * k);
            if (d > best)                 { best = d; bi = comp; }
            else if (d == best && comp < bi) bi = comp;
            dr[k] = 1e10f;
        }
        unsigned vb = __float_as_uint(best);
        unsigned m1 = __reduce_max_sync(0xFFFFFFFFu, vb);
        unsigned c1 = (vb == m1) ? bi : 0xFFFFFFFFu;
        unsigned i1 = __reduce_min_sync(0xFFFFFFFFu, c1);
        if (lane == 0) { initv[warp] = m1; initi[warp] = i1; }
    }
    __syncthreads();
    unsigned far;
    {
        unsigned v2 = (lane < NW) ? initv[lane] : 0u;
        unsigned i2 = (lane < NW) ? initi[lane] : 0xFFFFFFFFu;
        unsigned m2 = __reduce_max_sync(0xFFFFFFFFu, v2);
        unsigned c2 = (v2 == m2) ? i2 : 0xFFFFFFFFu;
        far = __reduce_min_sync(0xFFFFFFFFu, c2);
    }

    float* outp = out_pts + (size_t)b * MM * 3;
    int*   idxp = g_idx + b * MM;

    // Per-group cached state (exact while skipped): max-dr bits, min composite
    // among bit-equal ties, active interval [xlo, xhi]. All groups active on
    // the first iteration, which initializes everything.
    unsigned gvb[NG], gc[NG];
    float xlo[NG], xhi[NG];
    #pragma unroll
    for (int g = 0; g < NG; g++) {
        gvb[g] = __float_as_uint(1e10f); gc[g] = 0xFFFFFFFFu;
        xlo[g] = -1e30f; xhi[g] = 1e30f;
    }
    unsigned wvb = 0u, wcand = 0xFFFFFFFFu;   // combined cache (set on 1st iter)

    for (int m = 0; m < MM; m++) {
        const int buf = m & 1;
        // Broadcast the selected point via its rank (one LDS.128).
        float4 q = sq4[far & 0x1FFFu];
        if (tid == 0) {
            idxp[m] = (int)(far >> 13);
            outp[m * 3 + 0] = q.x;
            outp[m * 3 + 1] = q.y;
            outp[m * 3 + 2] = q.z;
        }

        // Interval prune per group: q.x outside [xmn-rw, xmx+rw] with
        // rw = sqrt(gmax)*1.0001 ==> dx^2 alone exceeds gmax by >1e-4 rel
        // (dwarfs <= ~6 ulp rounding) ==> every fminf in the group is a
        // bit-level no-op; all caches stay exact.
        bool any = false;
        bool act[NG];
        #pragma unroll
        for (int g = 0; g < NG; g++) {
            act[g] = (q.x >= xlo[g]) && (q.x <= xhi[g]);
            any |= act[g];
        }

        if (any) {
            #pragma unroll
            for (int g = 0; g < NG; g++) {
                if (act[g]) {
                    const int rbase = warp * (32 * PPT) + 128 * g + lane;
                    float mxg = -1.0f;
                    float4 p4[4];
                    #pragma unroll
                    for (int kk = 0; kk < 4; kk++) {
                        p4[kk] = sq4[rbase + 32 * kk];   // LDS.128, rank order
                        float dx = p4[kk].x - q.x;
                        float dy = p4[kk].y - q.y;
                        float dz = p4[kk].z - q.z;
                        float d = __fadd_rn(__fadd_rn(__fmul_rn(dx, dx),
                                                      __fmul_rn(dy, dy)),
                                            __fmul_rn(dz, dz));
                        float nd = fminf(dr[4 * g + kk], d);
                        dr[4 * g + kk] = nd;
                        mxg = fmaxf(mxg, nd);
                    }
                    gvb[g] = __reduce_max_sync(0xFFFFFFFFu, __float_as_uint(mxg));
                    unsigned cand = 0xFFFFFFFFu;
                    #pragma unroll
                    for (int kk = 0; kk < 4; kk++) {
                        if (__float_as_uint(dr[4 * g + kk]) == gvb[g]) {
                            unsigned comp = (__float_as_uint(p4[kk].w) << 13)
                                          | (unsigned)(rbase + 32 * kk);
                            cand = min(cand, comp);
                        }
                    }
                    gc[g] = __reduce_min_sync(0xFFFFFFFFu, cand);
                    // New active interval (group extent from smem; rare path).
                    float2 e = wext[warp * NG + g];      // warp-uniform LDS
                    float rw = __fmul_rn(__fsqrt_rn(__uint_as_float(gvb[g])),
                                         1.0001f);
                    xlo[g] = e.x - rw; xhi[g] = e.y + rw;
                }
            }
            // Recombine the warp-level cache (only when something changed).
            wvb = max(max(gvb[0], gvb[1]), max(gvb[2], gvb[3]));
            wcand = 0xFFFFFFFFu;
            #pragma unroll
            for (int g = 0; g < NG; g++)
                if (gvb[g] == wvb) wcand = min(wcand, gc[g]);
        }

        // Single-barrier block argmax over the NW cached (wvb, wcand) pairs.
        if (lane == 0) pvi[buf * NW + warp] = make_uint2(wvb, wcand);
        __syncthreads();
        uint2 p2 = pvi[buf * NW + (lane & (NW - 1))];    // dupes harmless
        unsigned m2 = __reduce_max_sync(0xFFFFFFFFu, p2.x);
        unsigned c2 = (p2.x == m2) ? p2.y : 0xFFFFFFFFu;
        far = __reduce_min_sync(0xFFFFFFFFu, c2);
    }
}

// Gather with channel-tiled blocks (indices preloaded to smem; coalesced
// writes; channel-plane reads get L1/L2 reuse).
#define CT 32            // channels per block
#define MT 512           // samples per block
extern "C" __global__ void __launch_bounds__(256)
gather_kernel(const float* __restrict__ feats,  // [B, C, N]
              float* __restrict__ out_feats)    // [B, M, C]
{
    __shared__ int sn[MT];
    int blk = blockIdx.x;                    // b * 32 + ct * 4 + mt
    int b   = blk >> 5;
    int ct  = (blk >> 2) & 7;                // 8 channel tiles
    int mt  = blk & 3;                       // 4 sample tiles
    int tid = threadIdx.x;

    for (int i = tid; i < MT; i += 256)
        sn[i] = g_idx[b * MM + mt * MT + i];
    __syncthreads();

    int c  = ct * CT + (tid & 31);
    int ml = tid >> 5;                       // 0..7
    const float* fp = feats + ((size_t)b * CC + c) * NN;
    float* op = out_feats + ((size_t)b * MM + mt * MT) * CC + c;

    #pragma unroll 4
    for (int mm = ml; mm < MT; mm += 8)
        op[(size_t)mm * CC] = fp[sn[mm]];
}

// Tiny kernel to keep ncu's "-s 5 -c 1" window on fps_kernel.
extern "C" __global__ void warm_kernel() {}

extern "C" void kernel_launch(void* const* d_in, const int* in_sizes, int n_in,
                              void* d_out, int out_size)
{
    const float* pts   = (const float*)d_in[0];  // [B, 3, N]
    const float* feats = (const float*)d_in[1];  // [B, C, N]
    float* out = (float*)d_out;

    cudaFuncSetAttribute(fps_kernel,
                         cudaFuncAttributeMaxDynamicSharedMemorySize, SMEM_BYTES);

    fps_kernel<<<BB, TT, SMEM_BYTES>>>(pts, out);
    warm_kernel<<<1, 1>>>();
    gather_kernel<<<BB * 32, 256>>>(feats, out + (size_t)BB * MM * 3);
}

// round 13
// speedup vs baseline: 1.7678x; 1.7678x over previous
#include <cuda_runtime.h>

// Problem constants (fixed: B=16, N=8192, C=256, num_points=2048)
#define BB   16
#define NN   8192
#define CC   256
#define MM   2048
#define TT   1024          // threads per FPS block
#define PPT  (NN / TT)     // points per thread = 8
#define NPAIR (PPT / 2)    // f32x2 pairs per thread = 4

// Scratch: selected indices, written by FPS kernel, read by gather kernel.
__device__ int g_idx[BB * MM];

// Dynamic smem: sq4[NN] float4 | pvi[64] uint2 | initv[32] | initi[32] |
//               cent[96] | wext[32] float2 | skx[NN] | ski[NN]
#define SMEM_BYTES (NN * 16 + 64 * 8 + 32 * 4 + 32 * 4 + 96 * 4 + 32 * 8 \
                    + NN * 4 + NN * 4)

// ---- packed f32x2 helpers (sm_103a) ---------------------------------------
__device__ __forceinline__ unsigned long long pack2(float lo, float hi) {
    unsigned long long r;
    asm("mov.b64 %0, {%1, %2};" : "=l"(r) : "f"(lo), "f"(hi));
    return r;
}
__device__ __forceinline__ void unpack2(unsigned long long v, float& lo, float& hi) {
    asm("mov.b64 {%0, %1}, %2;" : "=f"(lo), "=f"(hi) : "l"(v));
}
__device__ __forceinline__ unsigned long long add2(unsigned long long a, unsigned long long b) {
    unsigned long long r;
    asm("add.rn.f32x2 %0, %1, %2;" : "=l"(r) : "l"(a), "l"(b));
    return r;
}
__device__ __forceinline__ unsigned long long mul2(unsigned long long a, unsigned long long b) {
    unsigned long long r;
    asm("mul.rn.f32x2 %0, %1, %2;" : "=l"(r) : "l"(a), "l"(b));
    return r;
}
// ---------------------------------------------------------------------------

__device__ __forceinline__ float warp_sum(float x) {
    #pragma unroll
    for (int o = 16; o > 0; o >>= 1)
        x += __shfl_xor_sync(0xFFFFFFFFu, x, o);
    return x;
}
__device__ __forceinline__ float warp_min(float x) {
    #pragma unroll
    for (int o = 16; o > 0; o >>= 1)
        x = fminf(x, __shfl_xor_sync(0xFFFFFFFFu, x, o));
    return x;
}
__device__ __forceinline__ float warp_max(float x) {
    #pragma unroll
    for (int o = 16; o > 0; o >>= 1)
        x = fmaxf(x, __shfl_xor_sync(0xFFFFFFFFu, x, o));
    return x;
}

extern "C" __global__ void __launch_bounds__(TT, 1)
fps_kernel(const float* __restrict__ pts,   // [B, 3, N]
           float* __restrict__ out_pts)     // [B, M, 3]
{
    extern __shared__ unsigned char smraw[];
    float4*   sq4   = (float4*)smraw;                  // [NN] orig-indexed coords
    uint2*    pvi   = (uint2*)(smraw + NN * 16);       // [64] (val,cand), 2 bufs
    unsigned* initv = (unsigned*)(pvi + 64);           // [32]
    unsigned* initi = initv + 32;                      // [32]
    float*    cent  = (float*)(initi + 32);            // [96]
    float2*   wext  = (float2*)(cent + 96);            // [32] per-warp (xmn,xmx)
    float*    skx   = (float*)(wext + 32);             // [NN] sort keys (x)
    int*      ski   = (int*)(skx + NN);                // [NN] orig indices

    const int b    = blockIdx.x;
    const int tid  = threadIdx.x;
    const int lane = tid & 31;
    const int warp = tid >> 5;

    const float* px = pts + (size_t)b * 3 * NN;
    const float* py = px + NN;
    const float* pz = px + 2 * NN;

    // ---- load (orig layout), centroid sums, sort-key init ----
    float s1 = 0.f, s2 = 0.f, s3 = 0.f;
    #pragma unroll
    for (int k = 0; k < PPT; k++) {
        int n = tid + k * TT;               // coalesced
        float x = px[n], y = py[n], z = pz[n];
        sq4[n] = make_float4(x, y, z, 0.f);
        skx[n] = x; ski[n] = n;
        s1 += x; s2 += y; s3 += z;
    }

    // Deterministic centroid (exact, one-shot).
    s1 = warp_sum(s1); s2 = warp_sum(s2); s3 = warp_sum(s3);
    if (lane == 0) { cent[warp] = s1; cent[32 + warp] = s2; cent[64 + warp] = s3; }

    // ---- bitonic sort by x (permutation-preserving; quality only affects
    //      pruning, never correctness) ----
    for (int k = 2; k <= NN; k <<= 1) {
        for (int j = k >> 1; j > 0; j >>= 1) {
            __syncthreads();
            #pragma unroll 4
            for (int t = tid; t < NN / 2; t += TT) {
                int i = 2 * t - (t & (j - 1));
                int l = i + j;
                bool up = ((i & k) == 0);
                float a = skx[i], c = skx[l];
                bool sw = up ? (a > c) : (a < c);
                if (sw) {
                    skx[i] = c; skx[l] = a;
                    int ta = ski[i]; ski[i] = ski[l]; ski[l] = ta;
                }
            }
        }
    }
    __syncthreads();

    // ---- reorder into registers: warp w owns sorted ranks [256w, 256w+256) ----
    unsigned long long X2[NPAIR], Y2[NPAIR], Z2[NPAIR];
    unsigned OI2[NPAIR];                    // packed orig indices (lo | hi<<16)
    float dr[PPT];
    {
        float xs[PPT], ys[PPT], zs[PPT];
        unsigned oi[PPT];
        const int base = warp * 256 + lane;
        #pragma unroll
        for (int k = 0; k < PPT; k++) {
            int r = base + 32 * k;
            int idx = ski[r];
            float4 p = sq4[idx];
            xs[k] = p.x; ys[k] = p.y; zs[k] = p.z;
            oi[k] = (unsigned)idx;
            dr[k] = 1e10f;
        }
        #pragma unroll
        for (int j = 0; j < NPAIR; j++) {
            X2[j] = pack2(xs[2 * j], xs[2 * j + 1]);
            Y2[j] = pack2(ys[2 * j], ys[2 * j + 1]);
            Z2[j] = pack2(zs[2 * j], zs[2 * j + 1]);
            OI2[j] = oi[2 * j] | (oi[2 * j + 1] << 16);
        }
        // Warp x-extent (from held points) -> smem; read on rare update path.
        float xmn = xs[0], xmx = xs[0];
        #pragma unroll
        for (int k = 1; k < PPT; k++) {
            xmn = fminf(xmn, xs[k]); xmx = fmaxf(xmx, xs[k]);
        }
        xmn = warp_min(xmn); xmx = warp_max(xmx);
        if (lane == 0) wext[warp] = make_float2(xmn, xmx);

        // Centroid finalize.
        float cx = warp_sum(cent[lane])      * (1.0f / NN);
        float cy = warp_sum(cent[32 + lane]) * (1.0f / NN);
        float cz = warp_sum(cent[64 + lane]) * (1.0f / NN);

        // d0 = ||p - centroid||^2, initial farthest (exact plain form;
        // orig-idx tie-break since held points are no longer index-ordered).
        float best = -1.0f; unsigned bi = 0xFFFFFFFFu;
        #pragma unroll
        for (int k = 0; k < PPT; k++) {
            float dx = xs[k] - cx, dy = ys[k] - cy, dz = zs[k] - cz;
            float d = __fadd_rn(__fadd_rn(__fmul_rn(dx, dx), __fmul_rn(dy, dy)),
                                __fmul_rn(dz, dz));
            if (d > best)            { best = d; bi = oi[k]; }
            else if (d == best && oi[k] < bi) bi = oi[k];
        }
        unsigned vb = __float_as_uint(best);
        unsigned m1 = __reduce_max_sync(0xFFFFFFFFu, vb);
        unsigned c1 = (vb == m1) ? bi : 0xFFFFFFFFu;
        unsigned i1 = __reduce_min_sync(0xFFFFFFFFu, c1);
        if (lane == 0) { initv[warp] = m1; initi[warp] = i1; }
    }
    __syncthreads();
    unsigned far;
    {
        unsigned v2 = initv[lane];
        unsigned i2 = initi[lane];
        unsigned m2 = __reduce_max_sync(0xFFFFFFFFu, v2);
        unsigned c2 = (v2 == m2) ? i2 : 0xFFFFFFFFu;
        far = __reduce_min_sync(0xFFFFFFFFu, c2);
    }

    float* outp = out_pts + (size_t)b * MM * 3;
    int*   idxp = g_idx + b * MM;

    // Per-warp cached state (exact while skipped): max-dr bits, min orig idx
    // among bit-equal ties, and the active interval [xlo, xhi]. Infinite
    // interval -> first iteration always updates, initializing everything.
    unsigned wvb   = __float_as_uint(1e10f);
    unsigned wcand = 0xFFFFFFFFu;
    float xlo = -1e30f, xhi = 1e30f;

    for (int m = 0; m < MM; m++) {
        const int buf = m & 1;
        // Broadcast the selected point (one LDS.128, orig-indexed table).
        float4 q = sq4[far];
        if (tid == 0) {
            idxp[m] = (int)far;
            outp[m * 3 + 0] = q.x;
            outp[m * 3 + 1] = q.y;
            outp[m * 3 + 2] = q.z;
        }

        // Interval prune (2 setp): q.x outside [xmn-rw, xmx+rw] with
        // rw = sqrt(wmax)*1.0001 ==> dx^2 alone exceeds wmax by >1e-4 rel
        // (dwarfing <= ~6 ulp rounding) ==> every fminf below would be a
        // bit-level no-op; dr, wvb, wcand keep their exact values.
        if (q.x >= xlo && q.x <= xhi) {
            // Exact update (reference-rounded, no contraction).
            unsigned long long nqx2 = pack2(-q.x, -q.x);
            unsigned long long nqy2 = pack2(-q.y, -q.y);
            unsigned long long nqz2 = pack2(-q.z, -q.z);
            #pragma unroll
            for (int j = 0; j < NPAIR; j++) {
                unsigned long long dx2 = add2(X2[j], nqx2);
                unsigned long long dy2 = add2(Y2[j], nqy2);
                unsigned long long dz2 = add2(Z2[j], nqz2);
                unsigned long long d2 = add2(add2(mul2(dx2, dx2), mul2(dy2, dy2)),
                                             mul2(dz2, dz2));
                float dlo, dhi;
                unpack2(d2, dlo, dhi);
                dr[2 * j]     = fminf(dr[2 * j],     dlo);
                dr[2 * j + 1] = fminf(dr[2 * j + 1], dhi);
            }
            float a0 = fmaxf(dr[0], dr[1]);
            float a1 = fmaxf(dr[2], dr[3]);
            float a2 = fmaxf(dr[4], dr[5]);
            float a3 = fmaxf(dr[6], dr[7]);
            float mx = fmaxf(fmaxf(a0, a1), fmaxf(a2, a3));
            wvb = __reduce_max_sync(0xFFFFFFFFu, __float_as_uint(mx));
            // Min original index among bit-equal maxima (this warp).
            unsigned cand = 0xFFFFFFFFu;
            #pragma unroll
            for (int j = 0; j < NPAIR; j++) {
                if (__float_as_uint(dr[2 * j])     == wvb)
                    cand = min(cand, OI2[j] & 0xFFFFu);
                if (__float_as_uint(dr[2 * j + 1]) == wvb)
                    cand = min(cand, OI2[j] >> 16);
            }
            wcand = __reduce_min_sync(0xFFFFFFFFu, cand);
            // Refresh the active interval (extent from smem; rare path).
            float2 e = wext[warp];                       // warp-uniform LDS
            float rw = __fmul_rn(__fsqrt_rn(__uint_as_float(wvb)), 1.0001f);
            xlo = e.x - rw; xhi = e.y + rw;
        }

        // Single-barrier block argmax over the 32 cached (wvb, wcand) pairs.
        if (lane == 0) pvi[buf * 32 + warp] = make_uint2(wvb, wcand);
        __syncthreads();
        uint2 p2 = pvi[buf * 32 + lane];                 // LDS.64
        unsigned m2 = __reduce_max_sync(0xFFFFFFFFu, p2.x);
        unsigned c2 = (p2.x == m2) ? p2.y : 0xFFFFFFFFu;
        far = __reduce_min_sync(0xFFFFFFFFu, c2);
    }
}

// Gather with channel-tiled blocks (indices preloaded to smem; coalesced
// writes; channel-plane reads get L1/L2 reuse).
#define CT 32            // channels per block
#define MT 512           // samples per block
extern "C" __global__ void __launch_bounds__(256)
gather_kernel(const float* __restrict__ feats,  // [B, C, N]
              float* __restrict__ out_feats)    // [B, M, C]
{
    __shared__ int sn[MT];
    int blk = blockIdx.x;                    // b * 32 + ct * 4 + mt
    int b   = blk >> 5;
    int ct  = (blk >> 2) & 7;                // 8 channel tiles
    int mt  = blk & 3;                       // 4 sample tiles
    int tid = threadIdx.x;

    for (int i = tid; i < MT; i += 256)
        sn[i] = g_idx[b * MM + mt * MT + i];
    __syncthreads();

    int c  = ct * CT + (tid & 31);
    int ml = tid >> 5;                       // 0..7
    const float* fp = feats + ((size_t)b * CC + c) * NN;
    float* op = out_feats + ((size_t)b * MM + mt * MT) * CC + c;

    #pragma unroll 4
    for (int mm = ml; mm < MT; mm += 8)
        op[(size_t)mm * CC] = fp[sn[mm]];
}

// Tiny kernel to keep ncu's "-s 5 -c 1" window on fps_kernel.
extern "C" __global__ void warm_kernel() {}

extern "C" void kernel_launch(void* const* d_in, const int* in_sizes, int n_in,
                              void* d_out, int out_size)
{
    const float* pts   = (const float*)d_in[0];  // [B, 3, N]
    const float* feats = (const float*)d_in[1];  // [B, C, N]
    float* out = (float*)d_out;

    cudaFuncSetAttribute(fps_kernel,
                         cudaFuncAttributeMaxDynamicSharedMemorySize, SMEM_BYTES);

    fps_kernel<<<BB, TT, SMEM_BYTES>>>(pts, out);
    warm_kernel<<<1, 1>>>();
    gather_kernel<<<BB * 32, 256>>>(feats, out + (size_t)BB * MM * 3);
}